// round 15
// baseline (speedup 1.0000x reference)
#include <cuda_runtime.h>
#include <cuda_fp16.h>
#include <stdint.h>

// ---------------------------------------------------------------------------
// SSD head via mma.sync m16n8k16 FP16, round 15:
// One-shot NHWC-fp16 feature transpose (tiled) makes each A-tile row a
// contiguous 128B strip -> A loads become cp.async (no LDG gather, no
// convert, no STS in the hot loop). B image preprocessed as before.
// Main loop per chunk: cp.async A+B -> commit -> compute -> wait -> sync.
// 512 thr / 16 warps, warp = 2 m-tiles x 5 n-tiles, XOR-granule swizzle.
// Epilogue: acc -> smem -> bias + box decode + softmax fused.
// ---------------------------------------------------------------------------

#define NUM_PRIORS 11640
#define NTH 512
#define RS 128                          // smem row stride bytes (64 fp16, 8 granules)
#define NB 160                          // padded output channels (20 n-tiles)
#define ATILE (128 * RS)                // 16384
#define BTILE (NB * RS)                 // 20480
#define TOTAL_WCHUNKS 396
#define TOTAL_BLOCKS 488
#define A_OFF 0
#define B_OFF ATILE
#define BUFSZ (ATILE + BTILE)           // 36864
#define SMEM_BYTES 82944                // max(2*BUFSZ=73728, Dsm=128*161*4=82432)
#define DSTRIDE 161
#define FEAT16_ELEMS 37412864

__device__ __constant__ int d_C[6]    = {512,1024,512,256,256,256};
__device__ __constant__ int d_logC[6] = {9,10,9,8,8,8};
__device__ __constant__ int d_F[6]    = {38,19,10,5,3,1};
__device__ __constant__ int d_FF[6]   = {1444,361,100,25,9,1};
__device__ __constant__ int d_N[6]    = {46208,11552,3200,800,288,32};
__device__ __constant__ int d_nch[6]  = {72,144,72,36,36,36};
__device__ __constant__ int d_wch0[6] = {0,72,216,288,324,360};
__device__ __constant__ int d_poff[6] = {0,8664,10830,11430,11580,11634};
__device__ __constant__ int d_bstart[7] = {0,91,452,477,484,487,488};
__device__ __constant__ int d_border[6] = {1,0,2,3,4,5};
__device__ __constant__ size_t d_foff[6] =
    {0, 23658496, 35487744, 37126144, 37330944, 37404672};
// prep_feats block decomposition
__device__ __constant__ int d_fstart[7] = {0,23552,35840,37888,38144,38400,38656};
__device__ __constant__ int d_npt[6]   = {46,12,4,1,1,1};
__device__ __constant__ int d_nct[6]   = {16,32,16,8,8,8};
#define FEAT_BLOCKS 38656

__device__ unsigned char g_wbf[(size_t)TOTAL_WCHUNKS * BTILE];
__device__ __half g_feat16[FEAT16_ELEMS];
__device__ __align__(16) unsigned char g_zeropage[64];   // zero-initialized

struct WParams { const float* lw[6]; const float* cw[6]; };
struct CParams { const float* feat[6]; const float* lb[6]; const float* cb[6]; };

// ---- PTX helpers ------------------------------------------------------------
__device__ __forceinline__ uint32_t smaddr(const void* p) {
    return (uint32_t)__cvta_generic_to_shared(p);
}
__device__ __forceinline__ void ldsm4(uint32_t* r, uint32_t a) {
    asm volatile("ldmatrix.sync.aligned.m8n8.x4.shared.b16 {%0,%1,%2,%3}, [%4];"
                 : "=r"(r[0]), "=r"(r[1]), "=r"(r[2]), "=r"(r[3]) : "r"(a));
}
__device__ __forceinline__ void ldsm2(uint32_t* r, uint32_t a) {
    asm volatile("ldmatrix.sync.aligned.m8n8.x2.shared.b16 {%0,%1}, [%2];"
                 : "=r"(r[0]), "=r"(r[1]) : "r"(a));
}
__device__ __forceinline__ void mma_f16(float* d, const uint32_t* a, const uint32_t* b) {
    asm volatile("mma.sync.aligned.m16n8k16.row.col.f32.f16.f16.f32 "
                 "{%0,%1,%2,%3},{%4,%5,%6,%7},{%8,%9},{%0,%1,%2,%3};"
                 : "+f"(d[0]), "+f"(d[1]), "+f"(d[2]), "+f"(d[3])
                 : "r"(a[0]), "r"(a[1]), "r"(a[2]), "r"(a[3]),
                   "r"(b[0]), "r"(b[1]));
}
__device__ __forceinline__ void cpasync16(uint32_t dst, const void* src) {
    asm volatile("cp.async.cg.shared.global [%0], [%1], 16;"
                 :: "r"(dst), "l"(src) : "memory");
}
__device__ __forceinline__ void cpcommit() {
    asm volatile("cp.async.commit_group;" ::: "memory");
}
__device__ __forceinline__ void cpwait0() {
    asm volatile("cp.async.wait_group 0;" ::: "memory");
}

// swizzled byte offset of (row, 16B-granule g in 0..7) within a tile
__device__ __forceinline__ uint32_t swz(uint32_t row, uint32_t g) {
    return row * RS + ((g ^ (row & 7u)) << 4);
}

// ---- weight preprocessing: fp16, kk-major, swizzled rows --------------------
__global__ __launch_bounds__(256) void prep_weights(WParams P)
{
    int ch = blockIdx.x;
    int s = 0;
    #pragma unroll
    for (int i = 1; i < 6; i++) if (ch >= d_wch0[i]) s = i;
    int cis = ch - d_wch0[s];
    int C = d_C[s];
    int K = C * 9;
    int k0 = cis * 64;
    int kk = k0 >> d_logC[s];
    int c0 = k0 & (C - 1);
    size_t base = (size_t)ch * BTILE;

    for (int e = threadIdx.x; e < NB * 64; e += blockDim.x) {
        int row = e >> 6;
        int col = e & 63;
        float v = 0.f;
        if (row < 150) {
            int widx = (c0 + col) * 9 + kk;
            v = (row < 24) ? P.lw[s][(size_t)row * K + widx]
                           : P.cw[s][(size_t)(row - 24) * K + widx];
        }
        uint32_t off = swz(row, col >> 3) + (col & 7) * 2;
        *(__half*)(g_wbf + base + off) = __float2half_rn(v);
    }
}

// ---- feature transpose: NCHW f32 -> per-stage [b][p][C] fp16 ----------------
__global__ __launch_bounds__(256) void prep_feats(CParams P)
{
    __shared__ float tile[32][33];
    int bid = blockIdx.x;
    int s = 0;
    #pragma unroll
    for (int i = 1; i < 6; i++) if (bid >= d_fstart[i]) s = i;
    int local = bid - d_fstart[s];
    int nct = d_nct[s], npt = d_npt[s];
    int ct = local % nct;
    int pt = (local / nct) % npt;
    int b  = local / (nct * npt);

    const int C = d_C[s], FF = d_FF[s];
    const float* src = P.feat[s] + (size_t)b * C * FF;
    __half* dst = g_feat16 + d_foff[s] + (size_t)b * FF * C;

    int tx = threadIdx.x & 31;
    int ty = threadIdx.x >> 5;

    #pragma unroll
    for (int dy = 0; dy < 4; dy++) {
        int c = ct * 32 + ty + dy * 8;
        int p = pt * 32 + tx;
        tile[ty + dy * 8][tx] = (p < FF) ? src[(size_t)c * FF + p] : 0.f;
    }
    __syncthreads();
    #pragma unroll
    for (int dy = 0; dy < 4; dy++) {
        int p = pt * 32 + ty + dy * 8;
        int c = ct * 32 + tx;
        if (p < FF)
            dst[(size_t)p * C + c] = __float2half_rn(tile[tx][ty + dy * 8]);
    }
}

// ---- main fused kernel --------------------------------------------------------
__global__ __launch_bounds__(NTH, 1) void ssd_f16_kernel(
    CParams P, const float* __restrict__ priors, float* __restrict__ out)
{
    extern __shared__ __align__(16) unsigned char sm[];
    float* Dsm = (float*)sm;
    const uint32_t smb = smaddr(sm);

    const int tid = threadIdx.x;
    const int wid = tid >> 5;
    const int lane = tid & 31;
    const int mg = wid & 3;               // m-group: 32 pixels (2 m-tiles)
    const int ng = wid >> 2;              // n-group: 5 tiles
    const int gbase = ng * 5;

    // ---- block -> (stage, pixel tile) ----
    int bid = blockIdx.x;
    int oi = 0;
    #pragma unroll
    for (int i = 1; i < 6; i++) if (bid >= d_bstart[i]) oi = i;
    const int s = d_border[oi];
    const int pix0 = (bid - d_bstart[oi]) * 128;

    const int C = d_C[s], logC = d_logC[s], F = d_F[s], FF = d_FF[s], N = d_N[s];
    const int nch = d_nch[s], wch0 = d_wch0[s];

    // ---- A copy geometry: thread = (pixel row, granule pair) ----
    const int arow = tid & 127;             // pixel row in tile
    const int gi0  = (tid >> 7) * 2;        // first granule (0,2,4,6)
    const int apix = pix0 + arow;
    const bool aok = (apix < N);
    int ab = 0, ay = 0, ax = 0;
    if (aok) {
        ab = apix / FF;
        int r = apix - ab * FF;
        ay = r / F;
        ax = r - ay * F;
    }
    const __half* fb16 = g_feat16 + d_foff[s] + (size_t)ab * FF * C;

    // ---- ldmatrix lane components ----
    const int a_mloc = (lane & 7) + ((lane >> 3) & 1) * 8;
    const int a_kg   = lane >> 4;
    const int b_nloc = (lane & 7) + ((lane >> 4) & 1) * 8;
    const int b_kg   = (lane >> 3) & 1;

    float acc[2][5][4];
    #pragma unroll
    for (int mt = 0; mt < 2; mt++)
        #pragma unroll
        for (int nt = 0; nt < 5; nt++)
            #pragma unroll
            for (int q = 0; q < 4; q++) acc[mt][nt][q] = 0.f;

    // ---------------- helpers ----------------
    auto copyB = [&](int ch, int buf) {
        const uint4* src = (const uint4*)(g_wbf + (size_t)(wch0 + ch) * BTILE);
        uint32_t dst = smb + buf * BUFSZ + B_OFF;
        #pragma unroll
        for (int i = tid; i < BTILE / 16; i += NTH)
            cpasync16(dst + i * 16, src + i);
    };
    auto copyA = [&](int ch, int buf) {
        int k0 = ch * 64;
        int kk = k0 >> logC;
        int c0 = k0 & (C - 1);
        int ky = kk / 3, kx = kk - ky * 3;
        int iy = ay + ky - 1, ix = ax + kx - 1;
        bool v = aok && ((unsigned)iy < (unsigned)F) && ((unsigned)ix < (unsigned)F);
        const __half* src = v
            ? fb16 + ((size_t)(iy * F + ix)) * C + c0 + gi0 * 8
            : (const __half*)g_zeropage;
        const __half* src2 = v ? src + 8 : (const __half*)g_zeropage;
        uint32_t dbase = smb + buf * BUFSZ + A_OFF;
        cpasync16(dbase + swz((uint32_t)arow, (uint32_t)gi0),     src);
        cpasync16(dbase + swz((uint32_t)arow, (uint32_t)gi0 + 1), src2);
    };
    auto compute = [&](int buf) {
        const uint32_t aB = smb + buf * BUFSZ + A_OFF;
        const uint32_t bB = smb + buf * BUFSZ + B_OFF;
        uint32_t abase[2], amask[2];
        #pragma unroll
        for (int mt = 0; mt < 2; mt++) {
            uint32_t r = (uint32_t)(mg * 32 + mt * 16 + a_mloc);
            abase[mt] = aB + r * RS;
            amask[mt] = r & 7u;
        }
        uint32_t bbase[3], bmask[3];
        #pragma unroll
        for (int p = 0; p < 2; p++) {
            uint32_t r = (uint32_t)((gbase + p * 2) * 8 + b_nloc);
            bbase[p] = bB + r * RS;
            bmask[p] = r & 7u;
        }
        {
            uint32_t r = (uint32_t)((gbase + 4) * 8 + (lane & 7));
            bbase[2] = bB + r * RS;
            bmask[2] = r & 7u;
        }
        #pragma unroll
        for (int t = 0; t < 4; t++) {              // 4 k16 steps per chunk
            const uint32_t g0 = (uint32_t)t * 2;
            uint32_t a0[4], a1[4];
            ldsm4(a0, abase[0] + (((g0 + a_kg) ^ amask[0]) << 4));
            ldsm4(a1, abase[1] + (((g0 + a_kg) ^ amask[1]) << 4));
            uint32_t b0[4], b1[4], b2[2];
            ldsm4(b0, bbase[0] + (((g0 + b_kg) ^ bmask[0]) << 4));
            ldsm4(b1, bbase[1] + (((g0 + b_kg) ^ bmask[1]) << 4));
            ldsm2(b2, bbase[2] + (((g0 + b_kg) ^ bmask[2]) << 4));
            mma_f16(acc[0][0], a0, b0);
            mma_f16(acc[1][0], a1, b0);
            mma_f16(acc[0][1], a0, b0 + 2);
            mma_f16(acc[1][1], a1, b0 + 2);
            mma_f16(acc[0][2], a0, b1);
            mma_f16(acc[1][2], a1, b1);
            mma_f16(acc[0][3], a0, b1 + 2);
            mma_f16(acc[1][3], a1, b1 + 2);
            mma_f16(acc[0][4], a0, b2);
            mma_f16(acc[1][4], a1, b2);
        }
    };

    // ---------------- pipeline ----------------
    copyB(0, 0);
    copyA(0, 0);
    cpcommit();
    cpwait0();
    __syncthreads();

    for (int ch = 0; ch < nch; ch++) {
        int cur = ch & 1;
        bool pf = (ch + 1 < nch);
        if (pf) {
            copyB(ch + 1, cur ^ 1);
            copyA(ch + 1, cur ^ 1);
            cpcommit();
        }
        compute(cur);
        cpwait0();
        __syncthreads();
    }
    __syncthreads();                // compute done before Dsm overlays buffers

    // ---- write accumulators to smem D[128][DSTRIDE] ----
    #pragma unroll
    for (int mt = 0; mt < 2; mt++)
        #pragma unroll
        for (int nt = 0; nt < 5; nt++) {
            int r = mg * 32 + mt * 16 + (lane >> 2);
            int c = (gbase + nt) * 8 + (lane & 3) * 2;
            Dsm[r * DSTRIDE + c]           = acc[mt][nt][0];
            Dsm[r * DSTRIDE + c + 1]       = acc[mt][nt][1];
            Dsm[(r + 8) * DSTRIDE + c]     = acc[mt][nt][2];
            Dsm[(r + 8) * DSTRIDE + c + 1] = acc[mt][nt][3];
        }
    __syncthreads();

    // ---- per-pixel bias + decode + softmax ----
    if (tid < 128) {
        int n = pix0 + tid;
        if (n < N) {
            const float* drow = Dsm + tid * DSTRIDE;
            int b = n / FF;
            int r = n - b * FF;
            int pbase = d_poff[s] + r * 6;
            float* ob = out + ((size_t)b * NUM_PRIORS + pbase) * 25;
            const float* lb = P.lb[s];
            const float* cb = P.cb[s];
            #pragma unroll
            for (int pic = 0; pic < 6; pic++) {
                const float* pr = priors + (size_t)(pbase + pic) * 4;
                float prx = __ldg(pr + 0), pry = __ldg(pr + 1);
                float prz = __ldg(pr + 2), prw = __ldg(pr + 3);
                float lx = drow[pic * 4 + 0] + __ldg(lb + pic * 4 + 0);
                float ly = drow[pic * 4 + 1] + __ldg(lb + pic * 4 + 1);
                float lw_ = drow[pic * 4 + 2] + __ldg(lb + pic * 4 + 2);
                float lh_ = drow[pic * 4 + 3] + __ldg(lb + pic * 4 + 3);
                float cx = prx + lx * 0.1f * prz;
                float cy = pry + ly * 0.1f * prw;
                float w = prz * expf(lw_ * 0.2f);
                float h = prw * expf(lh_ * 0.2f);
                float mnx = cx - 0.5f * w;
                float mny = cy - 0.5f * h;
                float* o = ob + pic * 25;
                o[0] = mnx; o[1] = mny; o[2] = mnx + w; o[3] = mny + h;

                float vv[21];
                float mx = -1e30f;
                #pragma unroll
                for (int c2 = 0; c2 < 21; c2++) {
                    vv[c2] = drow[24 + pic * 21 + c2] + __ldg(cb + pic * 21 + c2);
                    mx = fmaxf(mx, vv[c2]);
                }
                float ssum = 0.f;
                #pragma unroll
                for (int c2 = 0; c2 < 21; c2++) { vv[c2] = expf(vv[c2] - mx); ssum += vv[c2]; }
                float inv = 1.f / ssum;
                #pragma unroll
                for (int c2 = 0; c2 < 21; c2++) o[4 + c2] = vv[c2] * inv;
            }
        }
    }
}

// ---------------------------------------------------------------------------
extern "C" void kernel_launch(void* const* d_in, const int* in_sizes, int n_in,
                              void* d_out, int out_size)
{
    CParams cp;
    WParams wp;
    const float* priors;

    bool interleaved = (n_in == 31) && (in_sizes[2] == 24);
    if (interleaved) {
        for (int s = 0; s < 6; s++) {
            cp.feat[s] = (const float*)d_in[s * 5 + 0];
            wp.lw[s]   = (const float*)d_in[s * 5 + 1];
            cp.lb[s]   = (const float*)d_in[s * 5 + 2];
            wp.cw[s]   = (const float*)d_in[s * 5 + 3];
            cp.cb[s]   = (const float*)d_in[s * 5 + 4];
        }
        priors = (const float*)d_in[30];
    } else {
        for (int s = 0; s < 6; s++) {
            cp.feat[s] = (const float*)d_in[s];
            wp.lw[s]   = (const float*)d_in[6 + s];
            cp.lb[s]   = (const float*)d_in[12 + s];
            wp.cw[s]   = (const float*)d_in[18 + s];
            cp.cb[s]   = (const float*)d_in[24 + s];
        }
        priors = (const float*)d_in[30];
    }

    cudaFuncSetAttribute(ssd_f16_kernel,
                         cudaFuncAttributeMaxDynamicSharedMemorySize, SMEM_BYTES);

    prep_weights<<<TOTAL_WCHUNKS, 256>>>(wp);
    prep_feats<<<FEAT_BLOCKS, 256>>>(cp);
    ssd_f16_kernel<<<TOTAL_BLOCKS, NTH, SMEM_BYTES>>>(cp, priors, (float*)d_out);
}

// round 16
// speedup vs baseline: 1.0759x; 1.0759x over previous
#include <cuda_runtime.h>
#include <cuda_fp16.h>
#include <stdint.h>

// ---------------------------------------------------------------------------
// SSD head via mma.sync m16n8k16 FP16, round 16:
// Round 15 (NHWC-fp16 one-shot transpose; A loads = cp.async of contiguous
// 128B strips) with the copyA lane mapping FIXED: 4 lanes per pixel so each
// warp loads 8 aligned 128B lines instead of 32 scattered ones.
// 512 thr / 16 warps, warp = 2 m-tiles x 5 n-tiles, XOR-granule swizzle.
// Epilogue: acc -> smem -> bias + box decode + softmax fused.
// ---------------------------------------------------------------------------

#define NUM_PRIORS 11640
#define NTH 512
#define RS 128                          // smem row stride bytes (64 fp16, 8 granules)
#define NB 160                          // padded output channels (20 n-tiles)
#define ATILE (128 * RS)                // 16384
#define BTILE (NB * RS)                 // 20480
#define TOTAL_WCHUNKS 396
#define TOTAL_BLOCKS 488
#define A_OFF 0
#define B_OFF ATILE
#define BUFSZ (ATILE + BTILE)           // 36864
#define SMEM_BYTES 82944                // max(2*BUFSZ=73728, Dsm=128*161*4=82432)
#define DSTRIDE 161
#define FEAT16_ELEMS 37412864

__device__ __constant__ int d_C[6]    = {512,1024,512,256,256,256};
__device__ __constant__ int d_logC[6] = {9,10,9,8,8,8};
__device__ __constant__ int d_F[6]    = {38,19,10,5,3,1};
__device__ __constant__ int d_FF[6]   = {1444,361,100,25,9,1};
__device__ __constant__ int d_N[6]    = {46208,11552,3200,800,288,32};
__device__ __constant__ int d_nch[6]  = {72,144,72,36,36,36};
__device__ __constant__ int d_wch0[6] = {0,72,216,288,324,360};
__device__ __constant__ int d_poff[6] = {0,8664,10830,11430,11580,11634};
__device__ __constant__ int d_bstart[7] = {0,91,452,477,484,487,488};
__device__ __constant__ int d_border[6] = {1,0,2,3,4,5};
__device__ __constant__ size_t d_foff[6] =
    {0, 23658496, 35487744, 37126144, 37330944, 37404672};
// prep_feats block decomposition
__device__ __constant__ int d_fstart[7] = {0,23552,35840,37888,38144,38400,38656};
__device__ __constant__ int d_npt[6]   = {46,12,4,1,1,1};
__device__ __constant__ int d_nct[6]   = {16,32,16,8,8,8};
#define FEAT_BLOCKS 38656

__device__ unsigned char g_wbf[(size_t)TOTAL_WCHUNKS * BTILE];
__device__ __half g_feat16[FEAT16_ELEMS];
__device__ __align__(16) unsigned char g_zeropage[64];   // zero-initialized

struct WParams { const float* lw[6]; const float* cw[6]; };
struct CParams { const float* feat[6]; const float* lb[6]; const float* cb[6]; };

// ---- PTX helpers ------------------------------------------------------------
__device__ __forceinline__ uint32_t smaddr(const void* p) {
    return (uint32_t)__cvta_generic_to_shared(p);
}
__device__ __forceinline__ void ldsm4(uint32_t* r, uint32_t a) {
    asm volatile("ldmatrix.sync.aligned.m8n8.x4.shared.b16 {%0,%1,%2,%3}, [%4];"
                 : "=r"(r[0]), "=r"(r[1]), "=r"(r[2]), "=r"(r[3]) : "r"(a));
}
__device__ __forceinline__ void ldsm2(uint32_t* r, uint32_t a) {
    asm volatile("ldmatrix.sync.aligned.m8n8.x2.shared.b16 {%0,%1}, [%2];"
                 : "=r"(r[0]), "=r"(r[1]) : "r"(a));
}
__device__ __forceinline__ void mma_f16(float* d, const uint32_t* a, const uint32_t* b) {
    asm volatile("mma.sync.aligned.m16n8k16.row.col.f32.f16.f16.f32 "
                 "{%0,%1,%2,%3},{%4,%5,%6,%7},{%8,%9},{%0,%1,%2,%3};"
                 : "+f"(d[0]), "+f"(d[1]), "+f"(d[2]), "+f"(d[3])
                 : "r"(a[0]), "r"(a[1]), "r"(a[2]), "r"(a[3]),
                   "r"(b[0]), "r"(b[1]));
}
__device__ __forceinline__ void cpasync16(uint32_t dst, const void* src) {
    asm volatile("cp.async.cg.shared.global [%0], [%1], 16;"
                 :: "r"(dst), "l"(src) : "memory");
}
__device__ __forceinline__ void cpcommit() {
    asm volatile("cp.async.commit_group;" ::: "memory");
}
__device__ __forceinline__ void cpwait0() {
    asm volatile("cp.async.wait_group 0;" ::: "memory");
}

// swizzled byte offset of (row, 16B-granule g in 0..7) within a tile
__device__ __forceinline__ uint32_t swz(uint32_t row, uint32_t g) {
    return row * RS + ((g ^ (row & 7u)) << 4);
}

// ---- weight preprocessing: fp16, kk-major, swizzled rows --------------------
__global__ __launch_bounds__(256) void prep_weights(WParams P)
{
    int ch = blockIdx.x;
    int s = 0;
    #pragma unroll
    for (int i = 1; i < 6; i++) if (ch >= d_wch0[i]) s = i;
    int cis = ch - d_wch0[s];
    int C = d_C[s];
    int K = C * 9;
    int k0 = cis * 64;
    int kk = k0 >> d_logC[s];
    int c0 = k0 & (C - 1);
    size_t base = (size_t)ch * BTILE;

    for (int e = threadIdx.x; e < NB * 64; e += blockDim.x) {
        int row = e >> 6;
        int col = e & 63;
        float v = 0.f;
        if (row < 150) {
            int widx = (c0 + col) * 9 + kk;
            v = (row < 24) ? P.lw[s][(size_t)row * K + widx]
                           : P.cw[s][(size_t)(row - 24) * K + widx];
        }
        uint32_t off = swz(row, col >> 3) + (col & 7) * 2;
        *(__half*)(g_wbf + base + off) = __float2half_rn(v);
    }
}

// ---- feature transpose: NCHW f32 -> per-stage [b][p][C] fp16 ----------------
__global__ __launch_bounds__(256) void prep_feats(CParams P)
{
    __shared__ float tile[32][33];
    int bid = blockIdx.x;
    int s = 0;
    #pragma unroll
    for (int i = 1; i < 6; i++) if (bid >= d_fstart[i]) s = i;
    int local = bid - d_fstart[s];
    int nct = d_nct[s], npt = d_npt[s];
    int ct = local % nct;
    int pt = (local / nct) % npt;
    int b  = local / (nct * npt);

    const int C = d_C[s], FF = d_FF[s];
    const float* src = P.feat[s] + (size_t)b * C * FF;
    __half* dst = g_feat16 + d_foff[s] + (size_t)b * FF * C;

    int tx = threadIdx.x & 31;
    int ty = threadIdx.x >> 5;

    #pragma unroll
    for (int dy = 0; dy < 4; dy++) {
        int c = ct * 32 + ty + dy * 8;
        int p = pt * 32 + tx;
        tile[ty + dy * 8][tx] = (p < FF) ? src[(size_t)c * FF + p] : 0.f;
    }
    __syncthreads();
    #pragma unroll
    for (int dy = 0; dy < 4; dy++) {
        int p = pt * 32 + ty + dy * 8;
        int c = ct * 32 + tx;
        if (p < FF)
            dst[(size_t)p * C + c] = __float2half_rn(tile[tx][ty + dy * 8]);
    }
}

// ---- main fused kernel --------------------------------------------------------
__global__ __launch_bounds__(NTH, 1) void ssd_f16_kernel(
    CParams P, const float* __restrict__ priors, float* __restrict__ out)
{
    extern __shared__ __align__(16) unsigned char sm[];
    float* Dsm = (float*)sm;
    const uint32_t smb = smaddr(sm);

    const int tid = threadIdx.x;
    const int wid = tid >> 5;
    const int lane = tid & 31;
    const int mg = wid & 3;               // m-group: 32 pixels (2 m-tiles)
    const int ng = wid >> 2;              // n-group: 5 tiles
    const int gbase = ng * 5;

    // ---- block -> (stage, pixel tile) ----
    int bid = blockIdx.x;
    int oi = 0;
    #pragma unroll
    for (int i = 1; i < 6; i++) if (bid >= d_bstart[i]) oi = i;
    const int s = d_border[oi];
    const int pix0 = (bid - d_bstart[oi]) * 128;

    const int C = d_C[s], logC = d_logC[s], F = d_F[s], FF = d_FF[s], N = d_N[s];
    const int nch = d_nch[s], wch0 = d_wch0[s];

    // ---- A copy geometry: 4 lanes per pixel (contiguous 128B strip) ----
    const int arow = tid >> 2;              // pixel row in tile (0..127)
    const int gi0  = (tid & 3) * 2;         // first granule (0,2,4,6)
    const int apix = pix0 + arow;
    const bool aok = (apix < N);
    int ab = 0, ay = 0, ax = 0;
    if (aok) {
        ab = apix / FF;
        int r = apix - ab * FF;
        ay = r / F;
        ax = r - ay * F;
    }
    const __half* fb16 = g_feat16 + d_foff[s] + (size_t)ab * FF * C;

    // ---- ldmatrix lane components ----
    const int a_mloc = (lane & 7) + ((lane >> 3) & 1) * 8;
    const int a_kg   = lane >> 4;
    const int b_nloc = (lane & 7) + ((lane >> 4) & 1) * 8;
    const int b_kg   = (lane >> 3) & 1;

    float acc[2][5][4];
    #pragma unroll
    for (int mt = 0; mt < 2; mt++)
        #pragma unroll
        for (int nt = 0; nt < 5; nt++)
            #pragma unroll
            for (int q = 0; q < 4; q++) acc[mt][nt][q] = 0.f;

    // ---------------- helpers ----------------
    auto copyB = [&](int ch, int buf) {
        const uint4* src = (const uint4*)(g_wbf + (size_t)(wch0 + ch) * BTILE);
        uint32_t dst = smb + buf * BUFSZ + B_OFF;
        #pragma unroll
        for (int i = tid; i < BTILE / 16; i += NTH)
            cpasync16(dst + i * 16, src + i);
    };
    auto copyA = [&](int ch, int buf) {
        int k0 = ch * 64;
        int kk = k0 >> logC;
        int c0 = k0 & (C - 1);
        int ky = kk / 3, kx = kk - ky * 3;
        int iy = ay + ky - 1, ix = ax + kx - 1;
        bool v = aok && ((unsigned)iy < (unsigned)F) && ((unsigned)ix < (unsigned)F);
        const __half* src = v
            ? fb16 + ((size_t)(iy * F + ix)) * C + c0 + gi0 * 8
            : (const __half*)g_zeropage;
        const __half* src2 = v ? src + 8 : (const __half*)g_zeropage;
        uint32_t dbase = smb + buf * BUFSZ + A_OFF;
        cpasync16(dbase + swz((uint32_t)arow, (uint32_t)gi0),     src);
        cpasync16(dbase + swz((uint32_t)arow, (uint32_t)gi0 + 1), src2);
    };
    auto compute = [&](int buf) {
        const uint32_t aB = smb + buf * BUFSZ + A_OFF;
        const uint32_t bB = smb + buf * BUFSZ + B_OFF;
        uint32_t abase[2], amask[2];
        #pragma unroll
        for (int mt = 0; mt < 2; mt++) {
            uint32_t r = (uint32_t)(mg * 32 + mt * 16 + a_mloc);
            abase[mt] = aB + r * RS;
            amask[mt] = r & 7u;
        }
        uint32_t bbase[3], bmask[3];
        #pragma unroll
        for (int p = 0; p < 2; p++) {
            uint32_t r = (uint32_t)((gbase + p * 2) * 8 + b_nloc);
            bbase[p] = bB + r * RS;
            bmask[p] = r & 7u;
        }
        {
            uint32_t r = (uint32_t)((gbase + 4) * 8 + (lane & 7));
            bbase[2] = bB + r * RS;
            bmask[2] = r & 7u;
        }
        #pragma unroll
        for (int t = 0; t < 4; t++) {              // 4 k16 steps per chunk
            const uint32_t g0 = (uint32_t)t * 2;
            uint32_t a0[4], a1[4];
            ldsm4(a0, abase[0] + (((g0 + a_kg) ^ amask[0]) << 4));
            ldsm4(a1, abase[1] + (((g0 + a_kg) ^ amask[1]) << 4));
            uint32_t b0[4], b1[4], b2[2];
            ldsm4(b0, bbase[0] + (((g0 + b_kg) ^ bmask[0]) << 4));
            ldsm4(b1, bbase[1] + (((g0 + b_kg) ^ bmask[1]) << 4));
            ldsm2(b2, bbase[2] + (((g0 + b_kg) ^ bmask[2]) << 4));
            mma_f16(acc[0][0], a0, b0);
            mma_f16(acc[1][0], a1, b0);
            mma_f16(acc[0][1], a0, b0 + 2);
            mma_f16(acc[1][1], a1, b0 + 2);
            mma_f16(acc[0][2], a0, b1);
            mma_f16(acc[1][2], a1, b1);
            mma_f16(acc[0][3], a0, b1 + 2);
            mma_f16(acc[1][3], a1, b1 + 2);
            mma_f16(acc[0][4], a0, b2);
            mma_f16(acc[1][4], a1, b2);
        }
    };

    // ---------------- pipeline ----------------
    copyB(0, 0);
    copyA(0, 0);
    cpcommit();
    cpwait0();
    __syncthreads();

    for (int ch = 0; ch < nch; ch++) {
        int cur = ch & 1;
        bool pf = (ch + 1 < nch);
        if (pf) {
            copyB(ch + 1, cur ^ 1);
            copyA(ch + 1, cur ^ 1);
            cpcommit();
        }
        compute(cur);
        cpwait0();
        __syncthreads();
    }
    __syncthreads();                // compute done before Dsm overlays buffers

    // ---- write accumulators to smem D[128][DSTRIDE] ----
    #pragma unroll
    for (int mt = 0; mt < 2; mt++)
        #pragma unroll
        for (int nt = 0; nt < 5; nt++) {
            int r = mg * 32 + mt * 16 + (lane >> 2);
            int c = (gbase + nt) * 8 + (lane & 3) * 2;
            Dsm[r * DSTRIDE + c]           = acc[mt][nt][0];
            Dsm[r * DSTRIDE + c + 1]       = acc[mt][nt][1];
            Dsm[(r + 8) * DSTRIDE + c]     = acc[mt][nt][2];
            Dsm[(r + 8) * DSTRIDE + c + 1] = acc[mt][nt][3];
        }
    __syncthreads();

    // ---- per-pixel bias + decode + softmax ----
    if (tid < 128) {
        int n = pix0 + tid;
        if (n < N) {
            const float* drow = Dsm + tid * DSTRIDE;
            int b = n / FF;
            int r = n - b * FF;
            int pbase = d_poff[s] + r * 6;
            float* ob = out + ((size_t)b * NUM_PRIORS + pbase) * 25;
            const float* lb = P.lb[s];
            const float* cb = P.cb[s];
            #pragma unroll
            for (int pic = 0; pic < 6; pic++) {
                const float* pr = priors + (size_t)(pbase + pic) * 4;
                float prx = __ldg(pr + 0), pry = __ldg(pr + 1);
                float prz = __ldg(pr + 2), prw = __ldg(pr + 3);
                float lx = drow[pic * 4 + 0] + __ldg(lb + pic * 4 + 0);
                float ly = drow[pic * 4 + 1] + __ldg(lb + pic * 4 + 1);
                float lw_ = drow[pic * 4 + 2] + __ldg(lb + pic * 4 + 2);
                float lh_ = drow[pic * 4 + 3] + __ldg(lb + pic * 4 + 3);
                float cx = prx + lx * 0.1f * prz;
                float cy = pry + ly * 0.1f * prw;
                float w = prz * expf(lw_ * 0.2f);
                float h = prw * expf(lh_ * 0.2f);
                float mnx = cx - 0.5f * w;
                float mny = cy - 0.5f * h;
                float* o = ob + pic * 25;
                o[0] = mnx; o[1] = mny; o[2] = mnx + w; o[3] = mny + h;

                float vv[21];
                float mx = -1e30f;
                #pragma unroll
                for (int c2 = 0; c2 < 21; c2++) {
                    vv[c2] = drow[24 + pic * 21 + c2] + __ldg(cb + pic * 21 + c2);
                    mx = fmaxf(mx, vv[c2]);
                }
                float ssum = 0.f;
                #pragma unroll
                for (int c2 = 0; c2 < 21; c2++) { vv[c2] = expf(vv[c2] - mx); ssum += vv[c2]; }
                float inv = 1.f / ssum;
                #pragma unroll
                for (int c2 = 0; c2 < 21; c2++) o[4 + c2] = vv[c2] * inv;
            }
        }
    }
}

// ---------------------------------------------------------------------------
extern "C" void kernel_launch(void* const* d_in, const int* in_sizes, int n_in,
                              void* d_out, int out_size)
{
    CParams cp;
    WParams wp;
    const float* priors;

    bool interleaved = (n_in == 31) && (in_sizes[2] == 24);
    if (interleaved) {
        for (int s = 0; s < 6; s++) {
            cp.feat[s] = (const float*)d_in[s * 5 + 0];
            wp.lw[s]   = (const float*)d_in[s * 5 + 1];
            cp.lb[s]   = (const float*)d_in[s * 5 + 2];
            wp.cw[s]   = (const float*)d_in[s * 5 + 3];
            cp.cb[s]   = (const float*)d_in[s * 5 + 4];
        }
        priors = (const float*)d_in[30];
    } else {
        for (int s = 0; s < 6; s++) {
            cp.feat[s] = (const float*)d_in[s];
            wp.lw[s]   = (const float*)d_in[6 + s];
            cp.lb[s]   = (const float*)d_in[12 + s];
            wp.cw[s]   = (const float*)d_in[18 + s];
            cp.cb[s]   = (const float*)d_in[24 + s];
        }
        priors = (const float*)d_in[30];
    }

    cudaFuncSetAttribute(ssd_f16_kernel,
                         cudaFuncAttributeMaxDynamicSharedMemorySize, SMEM_BYTES);

    prep_weights<<<TOTAL_WCHUNKS, 256>>>(wp);
    prep_feats<<<FEAT_BLOCKS, 256>>>(cp);
    ssd_f16_kernel<<<TOTAL_BLOCKS, NTH, SMEM_BYTES>>>(cp, priors, (float*)d_out);
}

// round 17
// speedup vs baseline: 1.6114x; 1.4977x over previous
#include <cuda_runtime.h>
#include <cuda_fp16.h>
#include <stdint.h>

// ---------------------------------------------------------------------------
// SSD head via mma.sync m16n8k16 FP16, round 17:
// Round-14 pipeline shape (A loads in registers during compute, STS after)
// + round-16 NHWC-fp16 prepped features (A row = contiguous 128B strip).
// Hot-loop A-prep per thread per chunk: 2x LDG.128 + 2x STS.128 (was
// 16 LDG + 8 cvt + 2 STS). B via cp.async from prepped weight image.
// 512 thr / 16 warps, warp = 2 m-tiles x 5 n-tiles, XOR-granule swizzle.
// Epilogue: acc -> smem -> bias + box decode + softmax fused.
// ---------------------------------------------------------------------------

#define NUM_PRIORS 11640
#define NTH 512
#define RS 128                          // smem row stride bytes (64 fp16, 8 granules)
#define NB 160                          // padded output channels (20 n-tiles)
#define ATILE (128 * RS)                // 16384
#define BTILE (NB * RS)                 // 20480
#define TOTAL_WCHUNKS 396
#define TOTAL_BLOCKS 488
#define A_OFF 0
#define B_OFF ATILE
#define BUFSZ (ATILE + BTILE)           // 36864
#define SMEM_BYTES 82944                // max(2*BUFSZ=73728, Dsm=128*161*4=82432)
#define DSTRIDE 161
#define FEAT16_ELEMS 37412864

__device__ __constant__ int d_C[6]    = {512,1024,512,256,256,256};
__device__ __constant__ int d_logC[6] = {9,10,9,8,8,8};
__device__ __constant__ int d_F[6]    = {38,19,10,5,3,1};
__device__ __constant__ int d_FF[6]   = {1444,361,100,25,9,1};
__device__ __constant__ int d_N[6]    = {46208,11552,3200,800,288,32};
__device__ __constant__ int d_nch[6]  = {72,144,72,36,36,36};
__device__ __constant__ int d_wch0[6] = {0,72,216,288,324,360};
__device__ __constant__ int d_poff[6] = {0,8664,10830,11430,11580,11634};
__device__ __constant__ int d_bstart[7] = {0,91,452,477,484,487,488};
__device__ __constant__ int d_border[6] = {1,0,2,3,4,5};
__device__ __constant__ size_t d_foff[6] =
    {0, 23658496, 35487744, 37126144, 37330944, 37404672};
// prep_feats block decomposition
__device__ __constant__ int d_fstart[7] = {0,23552,35840,37888,38144,38400,38656};
__device__ __constant__ int d_npt[6]   = {46,12,4,1,1,1};
__device__ __constant__ int d_nct[6]   = {16,32,16,8,8,8};
#define FEAT_BLOCKS 38656

__device__ unsigned char g_wbf[(size_t)TOTAL_WCHUNKS * BTILE];
__device__ __half g_feat16[FEAT16_ELEMS];

struct WParams { const float* lw[6]; const float* cw[6]; };
struct CParams { const float* feat[6]; const float* lb[6]; const float* cb[6]; };

// ---- PTX helpers ------------------------------------------------------------
__device__ __forceinline__ uint32_t smaddr(const void* p) {
    return (uint32_t)__cvta_generic_to_shared(p);
}
__device__ __forceinline__ void ldsm4(uint32_t* r, uint32_t a) {
    asm volatile("ldmatrix.sync.aligned.m8n8.x4.shared.b16 {%0,%1,%2,%3}, [%4];"
                 : "=r"(r[0]), "=r"(r[1]), "=r"(r[2]), "=r"(r[3]) : "r"(a));
}
__device__ __forceinline__ void ldsm2(uint32_t* r, uint32_t a) {
    asm volatile("ldmatrix.sync.aligned.m8n8.x2.shared.b16 {%0,%1}, [%2];"
                 : "=r"(r[0]), "=r"(r[1]) : "r"(a));
}
__device__ __forceinline__ void mma_f16(float* d, const uint32_t* a, const uint32_t* b) {
    asm volatile("mma.sync.aligned.m16n8k16.row.col.f32.f16.f16.f32 "
                 "{%0,%1,%2,%3},{%4,%5,%6,%7},{%8,%9},{%0,%1,%2,%3};"
                 : "+f"(d[0]), "+f"(d[1]), "+f"(d[2]), "+f"(d[3])
                 : "r"(a[0]), "r"(a[1]), "r"(a[2]), "r"(a[3]),
                   "r"(b[0]), "r"(b[1]));
}
__device__ __forceinline__ void cpasync16(uint32_t dst, const void* src) {
    asm volatile("cp.async.cg.shared.global [%0], [%1], 16;"
                 :: "r"(dst), "l"(src) : "memory");
}
__device__ __forceinline__ void cpcommit() {
    asm volatile("cp.async.commit_group;" ::: "memory");
}
__device__ __forceinline__ void cpwait0() {
    asm volatile("cp.async.wait_group 0;" ::: "memory");
}

// swizzled byte offset of (row, 16B-granule g in 0..7) within a tile
__device__ __forceinline__ uint32_t swz(uint32_t row, uint32_t g) {
    return row * RS + ((g ^ (row & 7u)) << 4);
}

// ---- weight preprocessing: fp16, kk-major, swizzled rows --------------------
__global__ __launch_bounds__(256) void prep_weights(WParams P)
{
    int ch = blockIdx.x;
    int s = 0;
    #pragma unroll
    for (int i = 1; i < 6; i++) if (ch >= d_wch0[i]) s = i;
    int cis = ch - d_wch0[s];
    int C = d_C[s];
    int K = C * 9;
    int k0 = cis * 64;
    int kk = k0 >> d_logC[s];
    int c0 = k0 & (C - 1);
    size_t base = (size_t)ch * BTILE;

    for (int e = threadIdx.x; e < NB * 64; e += blockDim.x) {
        int row = e >> 6;
        int col = e & 63;
        float v = 0.f;
        if (row < 150) {
            int widx = (c0 + col) * 9 + kk;
            v = (row < 24) ? P.lw[s][(size_t)row * K + widx]
                           : P.cw[s][(size_t)(row - 24) * K + widx];
        }
        uint32_t off = swz(row, col >> 3) + (col & 7) * 2;
        *(__half*)(g_wbf + base + off) = __float2half_rn(v);
    }
}

// ---- feature transpose: NCHW f32 -> per-stage [b][p][C] fp16 ----------------
__global__ __launch_bounds__(256) void prep_feats(CParams P)
{
    __shared__ float tile[32][33];
    int bid = blockIdx.x;
    int s = 0;
    #pragma unroll
    for (int i = 1; i < 6; i++) if (bid >= d_fstart[i]) s = i;
    int local = bid - d_fstart[s];
    int nct = d_nct[s], npt = d_npt[s];
    int ct = local % nct;
    int pt = (local / nct) % npt;
    int b  = local / (nct * npt);

    const int C = d_C[s], FF = d_FF[s];
    const float* src = P.feat[s] + (size_t)b * C * FF;
    __half* dst = g_feat16 + d_foff[s] + (size_t)b * FF * C;

    int tx = threadIdx.x & 31;
    int ty = threadIdx.x >> 5;

    #pragma unroll
    for (int dy = 0; dy < 4; dy++) {
        int c = ct * 32 + ty + dy * 8;
        int p = pt * 32 + tx;
        tile[ty + dy * 8][tx] = (p < FF) ? src[(size_t)c * FF + p] : 0.f;
    }
    __syncthreads();
    #pragma unroll
    for (int dy = 0; dy < 4; dy++) {
        int p = pt * 32 + ty + dy * 8;
        int c = ct * 32 + tx;
        if (p < FF)
            dst[(size_t)p * C + c] = __float2half_rn(tile[tx][ty + dy * 8]);
    }
}

// ---- main fused kernel --------------------------------------------------------
__global__ __launch_bounds__(NTH, 1) void ssd_f16_kernel(
    CParams P, const float* __restrict__ priors, float* __restrict__ out)
{
    extern __shared__ __align__(16) unsigned char sm[];
    float* Dsm = (float*)sm;
    const uint32_t smb = smaddr(sm);

    const int tid = threadIdx.x;
    const int wid = tid >> 5;
    const int lane = tid & 31;
    const int mg = wid & 3;               // m-group: 32 pixels (2 m-tiles)
    const int ng = wid >> 2;              // n-group: 5 tiles
    const int gbase = ng * 5;

    // ---- block -> (stage, pixel tile) ----
    int bid = blockIdx.x;
    int oi = 0;
    #pragma unroll
    for (int i = 1; i < 6; i++) if (bid >= d_bstart[i]) oi = i;
    const int s = d_border[oi];
    const int pix0 = (bid - d_bstart[oi]) * 128;

    const int C = d_C[s], logC = d_logC[s], F = d_F[s], FF = d_FF[s], N = d_N[s];
    const int nch = d_nch[s], wch0 = d_wch0[s];

    // ---- A geometry: 4 lanes per pixel (contiguous 128B strip) ----
    const int arow = tid >> 2;              // pixel row in tile (0..127)
    const int gi0  = (tid & 3) * 2;         // first granule (0,2,4,6)
    const int apix = pix0 + arow;
    const bool aok = (apix < N);
    int ab = 0, ay = 0, ax = 0;
    if (aok) {
        ab = apix / FF;
        int r = apix - ab * FF;
        ay = r / F;
        ax = r - ay * F;
    }
    const __half* fb16 = g_feat16 + d_foff[s] + (size_t)ab * FF * C;

    // ---- ldmatrix lane components ----
    const int a_mloc = (lane & 7) + ((lane >> 3) & 1) * 8;
    const int a_kg   = lane >> 4;
    const int b_nloc = (lane & 7) + ((lane >> 4) & 1) * 8;
    const int b_kg   = (lane >> 3) & 1;

    float acc[2][5][4];
    #pragma unroll
    for (int mt = 0; mt < 2; mt++)
        #pragma unroll
        for (int nt = 0; nt < 5; nt++)
            #pragma unroll
            for (int q = 0; q < 4; q++) acc[mt][nt][q] = 0.f;

    // ---------------- helpers ----------------
    auto copyB = [&](int ch, int buf) {
        const uint4* src = (const uint4*)(g_wbf + (size_t)(wch0 + ch) * BTILE);
        uint32_t dst = smb + buf * BUFSZ + B_OFF;
        #pragma unroll
        for (int i = tid; i < BTILE / 16; i += NTH)
            cpasync16(dst + i * 16, src + i);
    };
    uint4 ag0, ag1;                        // A strip in flight (8 regs)
    auto gatherA = [&](int ch) {
        int k0 = ch * 64;
        int kk = k0 >> logC;
        int c0 = k0 & (C - 1);
        int ky = kk / 3, kx = kk - ky * 3;
        int iy = ay + ky - 1, ix = ax + kx - 1;
        bool v = aok && ((unsigned)iy < (unsigned)F) && ((unsigned)ix < (unsigned)F);
        if (v) {
            const uint4* src = (const uint4*)(fb16 + ((size_t)(iy * F + ix)) * C
                                              + c0 + gi0 * 8);
            ag0 = __ldg(src);
            ag1 = __ldg(src + 1);
        } else {
            ag0 = make_uint4(0, 0, 0, 0);
            ag1 = make_uint4(0, 0, 0, 0);
        }
    };
    auto storeA = [&](int buf) {
        uint32_t dbase = smb + buf * BUFSZ + A_OFF;
        asm volatile("st.shared.v4.b32 [%0], {%1,%2,%3,%4};"
                     :: "r"(dbase + swz((uint32_t)arow, (uint32_t)gi0)),
                        "r"(ag0.x), "r"(ag0.y), "r"(ag0.z), "r"(ag0.w) : "memory");
        asm volatile("st.shared.v4.b32 [%0], {%1,%2,%3,%4};"
                     :: "r"(dbase + swz((uint32_t)arow, (uint32_t)gi0 + 1)),
                        "r"(ag1.x), "r"(ag1.y), "r"(ag1.z), "r"(ag1.w) : "memory");
    };
    auto compute = [&](int buf) {
        const uint32_t aB = smb + buf * BUFSZ + A_OFF;
        const uint32_t bB = smb + buf * BUFSZ + B_OFF;
        uint32_t abase[2], amask[2];
        #pragma unroll
        for (int mt = 0; mt < 2; mt++) {
            uint32_t r = (uint32_t)(mg * 32 + mt * 16 + a_mloc);
            abase[mt] = aB + r * RS;
            amask[mt] = r & 7u;
        }
        uint32_t bbase[3], bmask[3];
        #pragma unroll
        for (int p = 0; p < 2; p++) {
            uint32_t r = (uint32_t)((gbase + p * 2) * 8 + b_nloc);
            bbase[p] = bB + r * RS;
            bmask[p] = r & 7u;
        }
        {
            uint32_t r = (uint32_t)((gbase + 4) * 8 + (lane & 7));
            bbase[2] = bB + r * RS;
            bmask[2] = r & 7u;
        }
        #pragma unroll
        for (int t = 0; t < 4; t++) {              // 4 k16 steps per chunk
            const uint32_t g0 = (uint32_t)t * 2;
            uint32_t a0[4], a1[4];
            ldsm4(a0, abase[0] + (((g0 + a_kg) ^ amask[0]) << 4));
            ldsm4(a1, abase[1] + (((g0 + a_kg) ^ amask[1]) << 4));
            uint32_t b0[4], b1[4], b2[2];
            ldsm4(b0, bbase[0] + (((g0 + b_kg) ^ bmask[0]) << 4));
            ldsm4(b1, bbase[1] + (((g0 + b_kg) ^ bmask[1]) << 4));
            ldsm2(b2, bbase[2] + (((g0 + b_kg) ^ bmask[2]) << 4));
            mma_f16(acc[0][0], a0, b0);
            mma_f16(acc[1][0], a1, b0);
            mma_f16(acc[0][1], a0, b0 + 2);
            mma_f16(acc[1][1], a1, b0 + 2);
            mma_f16(acc[0][2], a0, b1);
            mma_f16(acc[1][2], a1, b1);
            mma_f16(acc[0][3], a0, b1 + 2);
            mma_f16(acc[1][3], a1, b1 + 2);
            mma_f16(acc[0][4], a0, b2);
            mma_f16(acc[1][4], a1, b2);
        }
    };

    // ---------------- pipeline ----------------
    copyB(0, 0);
    cpcommit();
    gatherA(0);
    storeA(0);
    cpwait0();
    __syncthreads();

    for (int ch = 0; ch < nch; ch++) {
        int cur = ch & 1;
        bool pf = (ch + 1 < nch);
        if (pf) {
            copyB(ch + 1, cur ^ 1);
            cpcommit();
            gatherA(ch + 1);        // LDG.128s in flight during MMAs
        }
        compute(cur);
        if (pf) storeA(cur ^ 1);    // two STS.128 after MMAs
        cpwait0();
        __syncthreads();
    }
    __syncthreads();                // compute done before Dsm overlays buffers

    // ---- write accumulators to smem D[128][DSTRIDE] ----
    #pragma unroll
    for (int mt = 0; mt < 2; mt++)
        #pragma unroll
        for (int nt = 0; nt < 5; nt++) {
            int r = mg * 32 + mt * 16 + (lane >> 2);
            int c = (gbase + nt) * 8 + (lane & 3) * 2;
            Dsm[r * DSTRIDE + c]           = acc[mt][nt][0];
            Dsm[r * DSTRIDE + c + 1]       = acc[mt][nt][1];
            Dsm[(r + 8) * DSTRIDE + c]     = acc[mt][nt][2];
            Dsm[(r + 8) * DSTRIDE + c + 1] = acc[mt][nt][3];
        }
    __syncthreads();

    // ---- per-pixel bias + decode + softmax ----
    if (tid < 128) {
        int n = pix0 + tid;
        if (n < N) {
            const float* drow = Dsm + tid * DSTRIDE;
            int b = n / FF;
            int r = n - b * FF;
            int pbase = d_poff[s] + r * 6;
            float* ob = out + ((size_t)b * NUM_PRIORS + pbase) * 25;
            const float* lb = P.lb[s];
            const float* cb = P.cb[s];
            #pragma unroll
            for (int pic = 0; pic < 6; pic++) {
                const float* pr = priors + (size_t)(pbase + pic) * 4;
                float prx = __ldg(pr + 0), pry = __ldg(pr + 1);
                float prz = __ldg(pr + 2), prw = __ldg(pr + 3);
                float lx = drow[pic * 4 + 0] + __ldg(lb + pic * 4 + 0);
                float ly = drow[pic * 4 + 1] + __ldg(lb + pic * 4 + 1);
                float lw_ = drow[pic * 4 + 2] + __ldg(lb + pic * 4 + 2);
                float lh_ = drow[pic * 4 + 3] + __ldg(lb + pic * 4 + 3);
                float cx = prx + lx * 0.1f * prz;
                float cy = pry + ly * 0.1f * prw;
                float w = prz * expf(lw_ * 0.2f);
                float h = prw * expf(lh_ * 0.2f);
                float mnx = cx - 0.5f * w;
                float mny = cy - 0.5f * h;
                float* o = ob + pic * 25;
                o[0] = mnx; o[1] = mny; o[2] = mnx + w; o[3] = mny + h;

                float vv[21];
                float mx = -1e30f;
                #pragma unroll
                for (int c2 = 0; c2 < 21; c2++) {
                    vv[c2] = drow[24 + pic * 21 + c2] + __ldg(cb + pic * 21 + c2);
                    mx = fmaxf(mx, vv[c2]);
                }
                float ssum = 0.f;
                #pragma unroll
                for (int c2 = 0; c2 < 21; c2++) { vv[c2] = expf(vv[c2] - mx); ssum += vv[c2]; }
                float inv = 1.f / ssum;
                #pragma unroll
                for (int c2 = 0; c2 < 21; c2++) o[4 + c2] = vv[c2] * inv;
            }
        }
    }
}

// ---------------------------------------------------------------------------
extern "C" void kernel_launch(void* const* d_in, const int* in_sizes, int n_in,
                              void* d_out, int out_size)
{
    CParams cp;
    WParams wp;
    const float* priors;

    bool interleaved = (n_in == 31) && (in_sizes[2] == 24);
    if (interleaved) {
        for (int s = 0; s < 6; s++) {
            cp.feat[s] = (const float*)d_in[s * 5 + 0];
            wp.lw[s]   = (const float*)d_in[s * 5 + 1];
            cp.lb[s]   = (const float*)d_in[s * 5 + 2];
            wp.cw[s]   = (const float*)d_in[s * 5 + 3];
            cp.cb[s]   = (const float*)d_in[s * 5 + 4];
        }
        priors = (const float*)d_in[30];
    } else {
        for (int s = 0; s < 6; s++) {
            cp.feat[s] = (const float*)d_in[s];
            wp.lw[s]   = (const float*)d_in[6 + s];
            cp.lb[s]   = (const float*)d_in[12 + s];
            wp.cw[s]   = (const float*)d_in[18 + s];
            cp.cb[s]   = (const float*)d_in[24 + s];
        }
        priors = (const float*)d_in[30];
    }

    cudaFuncSetAttribute(ssd_f16_kernel,
                         cudaFuncAttributeMaxDynamicSharedMemorySize, SMEM_BYTES);

    prep_weights<<<TOTAL_WCHUNKS, 256>>>(wp);
    prep_feats<<<FEAT_BLOCKS, 256>>>(cp);
    ssd_f16_kernel<<<TOTAL_BLOCKS, NTH, SMEM_BYTES>>>(cp, priors, (float*)d_out);
}